// round 16
// baseline (speedup 1.0000x reference)
#include <cuda_runtime.h>
#include <stdint.h>

// Sort_Latent_Layer: z (B, 1, 8192) fp32. Per row: 512 packets x 16 floats,
// stable-sort packets by packet[0] ascending, gather, write back.
//
// R15 = R14 (CTA-per-row, TMA staging, 4-warp bitonic, full-sector scatter)
// with two changes driven by the 76.8% L1 reading:
//   1. keys read from GLOBAL via __ldg (L2/MSHR-merged with the in-flight TMA
//      of the same sectors) -> removes the 512 bank-conflicted LDS wavefronts
//      per row that the smem key gather cost.
//   2. the bitonic sort runs BEFORE the TMA mbarrier wait -> sort latency is
//      hidden under the bulk copy; the wait guards only the scatter.

#define THREADS 128
#define ROW_BYTES 32768

#define OFF_SORT 32768                    // u64 ssort[512]  (4 KB)
#define OFF_SINV (OFF_SORT + 4096)        // u16 sinv[512]   (1 KB)
#define OFF_MBAR (OFF_SINV + 1024)
#define SMEM_TOTAL (OFF_MBAR + 16)

__device__ __forceinline__ uint32_t smem_u32(const void* p)
{
    uint32_t a;
    asm("{ .reg .u64 t; cvta.to.shared.u64 t, %1; cvt.u32.u64 %0, t; }"
        : "=r"(a) : "l"(p));
    return a;
}

__device__ __forceinline__ void mbar_wait0(uint32_t mbar)
{
    uint32_t done;
    asm volatile(
        "{\n\t.reg .pred p;\n\t"
        "mbarrier.try_wait.parity.acquire.cta.shared::cta.b64 p, [%1], 0;\n\t"
        "selp.b32 %0, 1, 0, p;\n\t}"
        : "=r"(done) : "r"(mbar) : "memory");
    if (!done) {
        asm volatile(
            "{\n\t.reg .pred P1;\n\t"
            "W_%=:\n\t"
            "mbarrier.try_wait.parity.acquire.cta.shared::cta.b64 P1, [%0], 0, 0x989680;\n\t"
            "@P1 bra.uni D_%=;\n\t"
            "bra.uni W_%=;\n\t"
            "D_%=:\n\t}"
            :: "r"(mbar) : "memory");
    }
}

__device__ __forceinline__ void ce(unsigned long long &x, unsigned long long &y, bool up)
{
    bool sw = (x > y) == up;          // items distinct (idx in low bits)
    unsigned long long a = sw ? y : x;
    unsigned long long b = sw ? x : y;
    x = a; y = b;
}

// one shfl stage over the 4 register items, distance dl lanes, comparator bit j
__device__ __forceinline__ void shfl_stage(unsigned long long it[4],
                                           int lane, int j, bool up)
{
    const int  dl      = j >> 2;
    const bool keepmin = (((lane * 4) & j) == 0) == up;
    #pragma unroll
    for (int v = 0; v < 4; ++v) {
        unsigned long long o = __shfl_xor_sync(0xFFFFFFFFu, it[v], dl);
        if ((o < it[v]) == keepmin) it[v] = o;
    }
}

__global__ void __launch_bounds__(THREADS)
sort_latent_r15(const float* __restrict__ z, float* __restrict__ out)
{
    extern __shared__ char smem[];
    float4*             sdata = (float4*)smem;
    unsigned long long* ssort = (unsigned long long*)(smem + OFF_SORT);
    uint16_t*           sinv  = (uint16_t*)(smem + OFF_SINV);
    const uint32_t      mbar  = smem_u32(smem + OFF_MBAR);

    const int t    = threadIdx.x;
    const int w    = t >> 5;
    const int lane = t & 31;
    const long long row = blockIdx.x;
    const float* __restrict__ zr = z + row * 8192;

    if (t == 0)
        asm volatile("mbarrier.init.shared.b64 [%0], 1;" :: "r"(mbar) : "memory");
    __syncthreads();
    if (t == 0) {
        asm volatile("mbarrier.arrive.expect_tx.shared.b64 _, [%0], %1;"
                     :: "r"(mbar), "r"(ROW_BYTES) : "memory");
        asm volatile(
            "cp.async.bulk.shared::cluster.global.mbarrier::complete_tx::bytes "
            "[%0], [%1], %2, [%3];"
            :: "r"(smem_u32(sdata)), "l"(zr), "r"(ROW_BYTES), "r"(mbar)
            : "memory");
    }

    // ---- keys from GLOBAL, overlapping the TMA (same sectors, L2-merged) ----
    const int i0 = w * 128 + lane * 4;
    unsigned long long it[4];
    #pragma unroll
    for (int v = 0; v < 4; ++v) {
        uint32_t kb = __float_as_uint(__ldg(zr + (i0 + v) * 16));
        kb = (kb & 0x80000000u) ? ~kb : (kb | 0x80000000u);   // monotone map
        it[v] = ((unsigned long long)kb << 32) | (unsigned)(i0 + v);
    }

    // ---- bitonic 512, 4-warp cooperative (runs while TMA streams) ----
    ce(it[0], it[1], true);
    ce(it[2], it[3], false);

    #pragma unroll
    for (int k = 4; k <= 64; k <<= 1) {
        const bool up = (((lane * 4) & k) == 0);
        #pragma unroll
        for (int j = k >> 1; j >= 4; j >>= 1)
            shfl_stage(it, lane, j, up);
        ce(it[0], it[2], up); ce(it[1], it[3], up);   // j=2
        ce(it[0], it[1], up); ce(it[2], it[3], up);   // j=1
    }

    {   // k = 128
        const bool up = ((w & 1) == 0);
        #pragma unroll
        for (int j = 64; j >= 4; j >>= 1)
            shfl_stage(it, lane, j, up);
        ce(it[0], it[2], up); ce(it[1], it[3], up);
        ce(it[0], it[1], up); ce(it[2], it[3], up);
    }

    {   // k = 256: j=128 via smem, then intra-warp
        const bool up = (w < 2);
        __syncthreads();
        #pragma unroll
        for (int v = 0; v < 4; ++v) ssort[i0 + v] = it[v];
        __syncthreads();
        #pragma unroll
        for (int v = 0; v < 4; ++v) {
            unsigned long long o = ssort[(i0 + v) ^ 128];
            bool keepmin = ((((i0 + v) & 128) == 0) == up);
            if ((o < it[v]) == keepmin) it[v] = o;
        }
        #pragma unroll
        for (int j = 64; j >= 4; j >>= 1)
            shfl_stage(it, lane, j, up);
        ce(it[0], it[2], up); ce(it[1], it[3], up);
        ce(it[0], it[1], up); ce(it[2], it[3], up);
    }

    {   // k = 512: j=256,128 via smem, then intra-warp; up = true
        #pragma unroll
        for (int j = 256; j >= 128; j >>= 1) {
            __syncthreads();
            #pragma unroll
            for (int v = 0; v < 4; ++v) ssort[i0 + v] = it[v];
            __syncthreads();
            #pragma unroll
            for (int v = 0; v < 4; ++v) {
                unsigned long long o = ssort[(i0 + v) ^ j];
                bool keepmin = (((i0 + v) & j) == 0);
                if ((o < it[v]) == keepmin) it[v] = o;
            }
        }
        #pragma unroll
        for (int j = 64; j >= 4; j >>= 1)
            shfl_stage(it, lane, j, true);
        ce(it[0], it[2], true); ce(it[1], it[3], true);
        ce(it[0], it[1], true); ce(it[2], it[3], true);
    }

    // ---- inverse permutation: sinv[src] = sorted position ----
    #pragma unroll
    for (int v = 0; v < 4; ++v)
        sinv[(int)(it[v] & 0x1FFu)] = (uint16_t)(i0 + v);

    // ---- wait for the staged row (first smem-data consumer), then scatter ----
    __syncthreads();                    // sinv visible to all warps
    mbar_wait0(mbar);                   // acquire; TMA done

    float4* __restrict__ out4 = (float4*)(out + row * 8192);
    #pragma unroll
    for (int half = 0; half < 2; ++half) {
        int    dst[8];
        float4 v4[8];
        #pragma unroll
        for (int u = 0; u < 8; ++u) {
            int f  = (half * 8 + u) * 128 + t;
            dst[u] = sinv[f >> 2];            // quad-broadcast LDS
            v4[u]  = sdata[f];                // linear, conflict-free LDS.128
        }
        #pragma unroll
        for (int u = 0; u < 8; ++u)
            __stcs(&out4[dst[u] * 4 + (t & 3)], v4[u]);   // full-sector 64B chunk
    }
}

extern "C" void kernel_launch(void* const* d_in, const int* in_sizes, int n_in,
                              void* d_out, int out_size)
{
    const float* z = (const float*)d_in[0];
    float* out     = (float*)d_out;
    const int D = 8192;                  // 512 packets * 16 floats
    int B = in_sizes[0] / D;             // 4096

    static int inited = 0;
    if (!inited) {
        cudaFuncSetAttribute(sort_latent_r15,
                             cudaFuncAttributeMaxDynamicSharedMemorySize,
                             SMEM_TOTAL);
        inited = 1;
    }
    sort_latent_r15<<<B, THREADS, SMEM_TOTAL>>>(z, out);
}

// round 17
// speedup vs baseline: 1.1162x; 1.1162x over previous
#include <cuda_runtime.h>
#include <stdint.h>

// Sort_Latent_Layer: z (B, 1, 8192) fp32. Per row: 512 packets x 16 floats,
// stable-sort packets by packet[0] ascending, gather, write back.
//
// R16: register-resident rows. CTA-per-row, 256 threads.
//   - load: 8 x float4 per thread, fully coalesced __ldcs. Keys are the .x of
//     quad-leader registers -> NO separate key read (R12-validated).
//   - sort: 8-warp cooperative bitonic, V=2 items/lane:
//       j=1        register compare-exchange
//       j=2..32    shfl_xor (dl = j/2)
//       j=64..256  smem exchange via ulonglong2 (STS.128/LDS.128, conflict-
//                  free) -- 6 stages total
//   - scatter: straight from registers, quad-contiguous 64B __stcs chunks
//     (full sectors, R12/R14-validated write shape).
//   Traffic = 128 MB coalesced reads + 128 MB full-sector writes = floor.
//   Smem only 7 KB (keys + sort + sinv) -> occupancy register-bound (~4 CTA/SM).

#define THREADS 256
#define NPK 512

__device__ __forceinline__ void ce(unsigned long long &x, unsigned long long &y, bool up)
{
    bool sw = (x > y) == up;          // items distinct (idx in low bits)
    unsigned long long a = sw ? y : x;
    unsigned long long b = sw ? x : y;
    x = a; y = b;
}

// shfl stage for V=2 blocked items (i = t*2 + v), comparator bit j in [2,32]
__device__ __forceinline__ void shfl2(unsigned long long it[2], int t, int j, bool up)
{
    const int  dl      = j >> 1;
    const bool keepmin = (((t & dl) == 0) == up);   // (i&j)==0  <=>  (t & j/2)==0
    #pragma unroll
    for (int v = 0; v < 2; ++v) {
        unsigned long long o = __shfl_xor_sync(0xFFFFFFFFu, it[v], dl);
        if ((o < it[v]) == keepmin) it[v] = o;
    }
}

__global__ void __launch_bounds__(THREADS)
sort_latent_r16(const float* __restrict__ z, float* __restrict__ out)
{
    __shared__ uint32_t           skey[NPK];        // 2 KB
    __shared__ unsigned long long ssort[NPK];       // 4 KB
    __shared__ uint16_t           sinv[NPK];        // 1 KB

    const int t = threadIdx.x;
    const long long row = blockIdx.x;

    const float4* __restrict__ in4  = (const float4*)(z   + row * 8192);
    float4* __restrict__       out4 = (float4*)(out + row * 8192);

    // ---- load row into registers, fully coalesced; keys come free ----
    float4 d[8];
    #pragma unroll
    for (int u = 0; u < 8; ++u)
        d[u] = __ldcs(&in4[u * 256 + t]);

    if ((t & 3) == 0) {                 // quad leader holds packet[0] in d[u].x
        #pragma unroll
        for (int u = 0; u < 8; ++u) {
            uint32_t kb = __float_as_uint(d[u].x);
            kb = (kb & 0x80000000u) ? ~kb : (kb | 0x80000000u);   // monotone map
            skey[u * 64 + (t >> 2)] = kb;
        }
    }
    __syncthreads();

    // ---- items: i = t*2 + v ----
    const int i0 = t * 2;
    unsigned long long it[2];
    {
        // contiguous pair -> single LDS.64-ish access pattern, near conflict-free
        it[0] = ((unsigned long long)skey[i0]     << 32) | (unsigned)i0;
        it[1] = ((unsigned long long)skey[i0 + 1] << 32) | (unsigned)(i0 + 1);
    }

    // ---- bitonic 512, 8-warp cooperative, V=2 ----
    // k = 2
    ce(it[0], it[1], (t & 1) == 0);

    // k = 4..64: fully intra-warp (max lane distance = 32/2 = 16... j=32 -> dl=16)
    #pragma unroll
    for (int k = 4; k <= 64; k <<= 1) {
        const bool up = ((t & (k >> 1)) == 0);
        #pragma unroll
        for (int j = k >> 1; j >= 2; j >>= 1)
            shfl2(it, t, j, up);
        ce(it[0], it[1], up);
    }

    // k = 128, 256, 512: j>=64 via smem (conflict-free ulonglong2), rest shfl
    #pragma unroll
    for (int k = 128; k <= 512; k <<= 1) {
        const bool up = ((t & (k >> 1)) == 0);      // k=512 -> always true
        #pragma unroll
        for (int j = k >> 1; j >= 64; j >>= 1) {
            __syncthreads();                        // prior ssort reads done
            ((ulonglong2*)ssort)[t] = make_ulonglong2(it[0], it[1]);
            __syncthreads();
            ulonglong2 q = ((ulonglong2*)ssort)[t ^ (j >> 1)];
            const bool keepmin = (((t & (j >> 1)) == 0) == up);
            if ((q.x < it[0]) == keepmin) it[0] = q.x;
            if ((q.y < it[1]) == keepmin) it[1] = q.y;
        }
        #pragma unroll
        for (int j = 32; j >= 2; j >>= 1)
            shfl2(it, t, j, up);
        ce(it[0], it[1], up);
    }

    // ---- inverse permutation: sinv[src] = sorted position ----
    sinv[(int)(it[0] & 0x1FFu)] = (uint16_t)i0;
    sinv[(int)(it[1] & 0x1FFu)] = (uint16_t)(i0 + 1);
    __syncthreads();

    // ---- scatter straight from registers (quad-contiguous 64B chunks) ----
    #pragma unroll
    for (int u = 0; u < 8; ++u) {
        int f   = u * 256 + t;
        int dst = sinv[f >> 2];                     // quad-broadcast LDS
        __stcs(&out4[dst * 4 + (t & 3)], d[u]);     // full-sector 64B chunk
    }
}

extern "C" void kernel_launch(void* const* d_in, const int* in_sizes, int n_in,
                              void* d_out, int out_size)
{
    const float* z = (const float*)d_in[0];
    float* out     = (float*)d_out;
    const int D = 8192;                  // 512 packets * 16 floats
    int B = in_sizes[0] / D;             // 4096

    sort_latent_r16<<<B, THREADS>>>(z, out);
}